// round 6
// baseline (speedup 1.0000x reference)
#include <cuda_runtime.h>
#include <cstdint>

#define NUSERS 100000
#define E 64
#define P 128
#define NSHARD 16
#define MSZ 512
#define WD 64
#define RR 4
#define INSZ 256
#define BB 256
#define SS 128
#define IND 384
#define QO 256

#define SCP 516
#define MSP 68

__device__ float g_pe[BB * P];
__device__ float g_q[(size_t)BB * SS * QO];
__device__ int g_uid[BB];
__device__ float g_memh[NSHARD * MSZ * WD];
__device__ float g_meml[NSHARD * MSZ * WD];

__global__ void k_uid(const int* __restrict__ u) {
    int s = 2;
#pragma unroll
    for (int i = 0; i < 8; i++)
        if (u[2 * i + 1] != 0) s = 1;
    int b = blockIdx.x * blockDim.x + threadIdx.x;
    if (b < BB) g_uid[b] = u[b * s];
}

__device__ __forceinline__ uint32_t t32(float x) {
    uint32_t u;
    asm("cvt.rna.tf32.f32 %0, %1;" : "=r"(u) : "f"(x));
    return u;
}
__device__ __forceinline__ void spl(float x, uint32_t& h, uint32_t& l) {
    h = t32(x);
    l = t32(x - __uint_as_float(h));
}
__device__ __forceinline__ void mma8(float d[4], const uint32_t a[4], uint32_t b0, uint32_t b1) {
    asm volatile(
        "mma.sync.aligned.m16n8k8.row.col.f32.tf32.tf32.f32 "
        "{%0,%1,%2,%3}, {%4,%5,%6,%7}, {%8,%9}, {%0,%1,%2,%3};"
        : "+f"(d[0]), "+f"(d[1]), "+f"(d[2]), "+f"(d[3])
        : "r"(a[0]), "r"(a[1]), "r"(a[2]), "r"(a[3]), "r"(b0), "r"(b1));
}

// --- pre-split memory into tf32 hi/lo ---
__global__ void k_split(const float* __restrict__ mem) {
    int i = blockIdx.x * blockDim.x + threadIdx.x;
    if (i < NSHARD * MSZ * WD) {
        float v = mem[i];
        uint32_t h, l;
        spl(v, h, l);
        g_memh[i] = __uint_as_float(h);
        g_meml[i] = __uint_as_float(l);
    }
}

__global__ void k_pe(const float* __restrict__ tab, const float* __restrict__ Wp,
                     const float* __restrict__ bp) {
    __shared__ float ue[E];
    int b = blockIdx.x;
    int t = threadIdx.x;
    int uid = g_uid[b];
    if (t < E) ue[t] = tab[(size_t)uid * E + t];
    __syncthreads();
    float acc = bp[t];
#pragma unroll
    for (int e = 0; e < E; e++) acc += ue[e] * Wp[e * P + t];
    g_pe[b * P + t] = acc;
}

// --- q = concat(x, pe) @ Wq[sid] via mma.sync tf32, stage-time hi/lo split ---
// grid (4 n-tiles, 2 m-tiles, B), 256 threads. 64x64 tile, warp = 16x32.
__global__ __launch_bounds__(256) void k_qgemm(const float* __restrict__ x,
                                               const float* __restrict__ Wq) {
    __shared__ float Ash[64][36], Asl[64][36];
    __shared__ float Bsh[32][68], Bsl[32][68];
    int b = blockIdx.z;
    int n0 = blockIdx.x * 64, m0 = blockIdx.y * 64;
    int sid = ((unsigned)g_uid[b]) % NSHARD;
    const float* Wg = Wq + (size_t)sid * IND * QO;
    int tid = threadIdx.x;
    int lane = tid & 31, warp = tid >> 5;
    int g = lane >> 2, c = lane & 3;
    int wm = warp & 3, wn = warp >> 2;
    const float* xb = x + ((size_t)b * SS + m0) * INSZ;
    const float* pe = g_pe + b * P;

    float d[4][4];
#pragma unroll
    for (int i = 0; i < 4; i++)
#pragma unroll
        for (int j = 0; j < 4; j++) d[i][j] = 0.f;

    for (int k0 = 0; k0 < IND; k0 += 32) {
        // stage A 64x32 (hi/lo)
        for (int i = tid; i < 64 * 8; i += 256) {
            int row = i >> 3, k4 = (i & 7) * 4;
            float4 v;
            if (k0 < INSZ) v = *(const float4*)&xb[row * INSZ + k0 + k4];
            else v = *(const float4*)&pe[k0 - INSZ + k4];
            uint32_t hx, lx, hy, ly, hz, lz, hw, lw;
            spl(v.x, hx, lx); spl(v.y, hy, ly); spl(v.z, hz, lz); spl(v.w, hw, lw);
            Ash[row][k4] = __uint_as_float(hx); Ash[row][k4 + 1] = __uint_as_float(hy);
            Ash[row][k4 + 2] = __uint_as_float(hz); Ash[row][k4 + 3] = __uint_as_float(hw);
            Asl[row][k4] = __uint_as_float(lx); Asl[row][k4 + 1] = __uint_as_float(ly);
            Asl[row][k4 + 2] = __uint_as_float(lz); Asl[row][k4 + 3] = __uint_as_float(lw);
        }
        // stage B 32x64 (hi/lo), rows = k
        for (int i = tid; i < 32 * 16; i += 256) {
            int kk = i >> 4, n4 = (i & 15) * 4;
            float4 v = *(const float4*)&Wg[(size_t)(k0 + kk) * QO + n0 + n4];
            uint32_t hx, lx, hy, ly, hz, lz, hw, lw;
            spl(v.x, hx, lx); spl(v.y, hy, ly); spl(v.z, hz, lz); spl(v.w, hw, lw);
            Bsh[kk][n4] = __uint_as_float(hx); Bsh[kk][n4 + 1] = __uint_as_float(hy);
            Bsh[kk][n4 + 2] = __uint_as_float(hz); Bsh[kk][n4 + 3] = __uint_as_float(hw);
            Bsl[kk][n4] = __uint_as_float(lx); Bsl[kk][n4 + 1] = __uint_as_float(ly);
            Bsl[kk][n4 + 2] = __uint_as_float(lz); Bsl[kk][n4 + 3] = __uint_as_float(lw);
        }
        __syncthreads();
#pragma unroll
        for (int ks = 0; ks < 4; ks++) {
            uint32_t ah[4], al[4];
            ah[0] = __float_as_uint(Ash[wm * 16 + g][ks * 8 + c]);
            ah[1] = __float_as_uint(Ash[wm * 16 + g + 8][ks * 8 + c]);
            ah[2] = __float_as_uint(Ash[wm * 16 + g][ks * 8 + c + 4]);
            ah[3] = __float_as_uint(Ash[wm * 16 + g + 8][ks * 8 + c + 4]);
            al[0] = __float_as_uint(Asl[wm * 16 + g][ks * 8 + c]);
            al[1] = __float_as_uint(Asl[wm * 16 + g + 8][ks * 8 + c]);
            al[2] = __float_as_uint(Asl[wm * 16 + g][ks * 8 + c + 4]);
            al[3] = __float_as_uint(Asl[wm * 16 + g + 8][ks * 8 + c + 4]);
#pragma unroll
            for (int nt = 0; nt < 4; nt++) {
                int nn = wn * 32 + nt * 8;
                uint32_t bh0 = __float_as_uint(Bsh[ks * 8 + c][nn + g]);
                uint32_t bh1 = __float_as_uint(Bsh[ks * 8 + c + 4][nn + g]);
                uint32_t bl0 = __float_as_uint(Bsl[ks * 8 + c][nn + g]);
                uint32_t bl1 = __float_as_uint(Bsl[ks * 8 + c + 4][nn + g]);
                mma8(d[nt], ah, bh0, bh1);
                mma8(d[nt], ah, bl0, bl1);
                mma8(d[nt], al, bh0, bh1);
            }
        }
        __syncthreads();
    }
    float* qb = g_q + ((size_t)b * SS + m0) * QO + n0;
#pragma unroll
    for (int nt = 0; nt < 4; nt++) {
        int nn = wn * 32 + nt * 8 + 2 * c;
        float2 v01 = {d[nt][0], d[nt][1]};
        float2 v23 = {d[nt][2], d[nt][3]};
        *(float2*)&qb[(size_t)(wm * 16 + g) * QO + nn] = v01;
        *(float2*)&qb[(size_t)(wm * 16 + g + 8) * QO + nn] = v23;
    }
}

// ---------------- fused attention: R4 structure + pre-split B ----------------
// block = (b, 8 s-positions) = 32 rows. grid (16, B), 256 threads, 1 CTA/SM.
__global__ __launch_bounds__(256, 1) void k_attn(float* __restrict__ out) {
    extern __shared__ float sm[];
    float* sc = sm;                   // [32][516]
    float* msh = sc + 32 * SCP;       // [128][68]
    float* msl = msh + 128 * MSP;     // [128][68]
    float* qs = msl + 128 * MSP;      // [32][68]

    int tid = threadIdx.x;
    int lane = tid & 31, warp = tid >> 5;
    int g = lane >> 2, c = lane & 3;
    int rt = warp >> 2;
    int wq = warp & 3;
    int b = blockIdx.y;
    int s0 = blockIdx.x * 8;
    int sid = ((unsigned)g_uid[b]) % NSHARD;
    const float* Mh = g_memh + (size_t)sid * MSZ * WD;
    const float* Ml = g_meml + (size_t)sid * MSZ * WD;

    const float* qsrc = g_q + ((size_t)b * SS + s0) * QO;
    for (int i = tid; i < 32 * 16; i += 256) {
        int row = i >> 4, w4 = (i & 15) * 4;
        float4 v = *(const float4*)&qsrc[(size_t)(row >> 2) * QO + (row & 3) * WD + w4];
        *(float4*)&qs[row * MSP + w4] = v;
    }

    uint32_t ah[8][4], al[8][4];

    // ---- phase 1: scores[32,512], chunks of 128 m ----
    for (int ch = 0; ch < 4; ch++) {
        for (int i = tid; i < 128 * 16; i += 256) {
            int m = i >> 4, w4 = (i & 15) * 4;
            size_t go = (size_t)(ch * 128 + m) * WD + w4;
            *(float4*)&msh[m * MSP + w4] = *(const float4*)&Mh[go];
            *(float4*)&msl[m * MSP + w4] = *(const float4*)&Ml[go];
        }
        __syncthreads();
        if (ch == 0) {
#pragma unroll
            for (int k = 0; k < 8; k++) {
                float a0 = qs[(rt * 16 + g) * MSP + k * 8 + c];
                float a1 = qs[(rt * 16 + g + 8) * MSP + k * 8 + c];
                float a2 = qs[(rt * 16 + g) * MSP + k * 8 + c + 4];
                float a3 = qs[(rt * 16 + g + 8) * MSP + k * 8 + c + 4];
                spl(a0, ah[k][0], al[k][0]);
                spl(a1, ah[k][1], al[k][1]);
                spl(a2, ah[k][2], al[k][2]);
                spl(a3, ah[k][3], al[k][3]);
            }
        }
#pragma unroll
        for (int nt = 0; nt < 4; nt++) {
            int n0 = wq * 32 + nt * 8;
            float d[4] = {0.f, 0.f, 0.f, 0.f};
#pragma unroll
            for (int k = 0; k < 8; k++) {
                uint32_t bh0 = __float_as_uint(msh[(n0 + g) * MSP + k * 8 + c]);
                uint32_t bh1 = __float_as_uint(msh[(n0 + g) * MSP + k * 8 + c + 4]);
                uint32_t bl0 = __float_as_uint(msl[(n0 + g) * MSP + k * 8 + c]);
                uint32_t bl1 = __float_as_uint(msl[(n0 + g) * MSP + k * 8 + c + 4]);
                mma8(d, ah[k], bh0, bh1);
                mma8(d, ah[k], bl0, bl1);
                mma8(d, al[k], bh0, bh1);
            }
            int mg = ch * 128 + n0 + 2 * c;
            float2 v01 = {d[0], d[1]};
            float2 v23 = {d[2], d[3]};
            *(float2*)&sc[(rt * 16 + g) * SCP + mg] = v01;
            *(float2*)&sc[(rt * 16 + g + 8) * SCP + mg] = v23;
        }
        __syncthreads();
    }

    // ---- softmax ----
    for (int rr = 0; rr < 4; rr++) {
        int row = warp * 4 + rr;
        float* srow = sc + row * SCP;
        float vals[16];
        float mx = -1e30f;
#pragma unroll
        for (int j = 0; j < 16; j++) {
            vals[j] = srow[lane + 32 * j];
            mx = fmaxf(mx, vals[j]);
        }
#pragma unroll
        for (int o = 16; o > 0; o >>= 1) mx = fmaxf(mx, __shfl_xor_sync(0xffffffffu, mx, o));
        float sum = 0.f;
#pragma unroll
        for (int j = 0; j < 16; j++) {
            vals[j] = __expf(vals[j] - mx);
            sum += vals[j];
        }
#pragma unroll
        for (int o = 16; o > 0; o >>= 1) sum += __shfl_xor_sync(0xffffffffu, sum, o);
        float inv = 1.f / sum;
#pragma unroll
        for (int j = 0; j < 16; j++) srow[lane + 32 * j] = vals[j] * inv;
        if (b == BB - 1) {
            float* fs = out + (size_t)BB * SS * RR * WD + (size_t)(s0 * 4 + row) * MSZ;
#pragma unroll
            for (int j = 0; j < 16; j++) fs[lane + 32 * j] = vals[j] * inv;
        }
    }

    // ---- phase 2: read = wts @ mem, 2-pass ----
    float acc[2][4];
#pragma unroll
    for (int nt = 0; nt < 2; nt++)
#pragma unroll
        for (int j = 0; j < 4; j++) acc[nt][j] = 0.f;

    for (int ch = 0; ch < 4; ch++) {
        __syncthreads();
        for (int i = tid; i < 128 * 16; i += 256) {
            int m = i >> 4, w4 = (i & 15) * 4;
            size_t go = (size_t)(ch * 128 + m) * WD + w4;
            *(float4*)&msh[m * MSP + w4] = *(const float4*)&Mh[go];
            *(float4*)&msl[m * MSP + w4] = *(const float4*)&Ml[go];
        }
        __syncthreads();
#pragma unroll
        for (int kt = 0; kt < 16; kt++) {
            int kg = ch * 128 + kt * 8;
            uint32_t wh[4];
            wh[0] = t32(sc[(rt * 16 + g) * SCP + kg + c]);
            wh[1] = t32(sc[(rt * 16 + g + 8) * SCP + kg + c]);
            wh[2] = t32(sc[(rt * 16 + g) * SCP + kg + c + 4]);
            wh[3] = t32(sc[(rt * 16 + g + 8) * SCP + kg + c + 4]);
#pragma unroll
            for (int nt = 0; nt < 2; nt++) {
                int n0 = wq * 16 + nt * 8;
                uint32_t bh0 = __float_as_uint(msh[(kt * 8 + c) * MSP + n0 + g]);
                uint32_t bh1 = __float_as_uint(msh[(kt * 8 + c + 4) * MSP + n0 + g]);
                uint32_t bl0 = __float_as_uint(msl[(kt * 8 + c) * MSP + n0 + g]);
                uint32_t bl1 = __float_as_uint(msl[(kt * 8 + c + 4) * MSP + n0 + g]);
                mma8(acc[nt], wh, bh0, bh1);
                mma8(acc[nt], wh, bl0, bl1);
            }
        }
    }

    float* ob = out + ((size_t)b * 512 + s0 * 4) * WD;
#pragma unroll
    for (int nt = 0; nt < 2; nt++) {
        int wcol = wq * 16 + nt * 8 + 2 * c;
        float2 v01 = {acc[nt][0], acc[nt][1]};
        float2 v23 = {acc[nt][2], acc[nt][3]};
        *(float2*)&ob[(size_t)(rt * 16 + g) * WD + wcol] = v01;
        *(float2*)&ob[(size_t)(rt * 16 + g + 8) * WD + wcol] = v23;
    }
}

extern "C" void kernel_launch(void* const* d_in, const int* in_sizes, int n_in,
                              void* d_out, int out_size) {
    const float* x = (const float*)d_in[0];
    const int* uid = (const int*)d_in[1];
    const float* tab = (const float*)d_in[2];
    const float* Wp = (const float*)d_in[3];
    const float* bp = (const float*)d_in[4];
    const float* Wq = (const float*)d_in[5];
    const float* memp = (const float*)d_in[6];
    float* out = (float*)d_out;

    k_uid<<<1, 256>>>(uid);
    k_split<<<(NSHARD * MSZ * WD + 511) / 512, 512>>>(memp);
    k_pe<<<BB, 128>>>(tab, Wp, bp);
    dim3 g2(4, 2, BB);
    k_qgemm<<<g2, 256>>>(x, Wq);

    const int smem_bytes = (32 * SCP + 2 * 128 * MSP + 32 * MSP) * 4;
    cudaFuncSetAttribute(k_attn, cudaFuncAttributeMaxDynamicSharedMemorySize, smem_bytes);
    dim3 g3(16, BB);
    k_attn<<<g3, 256, smem_bytes>>>(out);
}

// round 7
// speedup vs baseline: 1.3325x; 1.3325x over previous
#include <cuda_runtime.h>
#include <cstdint>

#define NUSERS 100000
#define E 64
#define P 128
#define NSHARD 16
#define MSZ 512
#define WD 64
#define RR 4
#define INSZ 256
#define BB 256
#define SS 128
#define IND 384
#define QO 256

#define SCP 516
#define MSP 68

__device__ float g_pe[BB * P];
__device__ float g_q[(size_t)BB * SS * QO];
__device__ int g_uid[BB];

__global__ void k_uid(const int* __restrict__ u) {
    int s = 2;
#pragma unroll
    for (int i = 0; i < 8; i++)
        if (u[2 * i + 1] != 0) s = 1;
    int b = blockIdx.x * blockDim.x + threadIdx.x;
    if (b < BB) g_uid[b] = u[b * s];
}

__device__ __forceinline__ uint32_t t32(float x) {
    uint32_t u;
    asm("cvt.rna.tf32.f32 %0, %1;" : "=r"(u) : "f"(x));
    return u;
}
__device__ __forceinline__ void spl(float x, uint32_t& h, uint32_t& l) {
    h = t32(x);
    l = t32(x - __uint_as_float(h));
}
__device__ __forceinline__ void mma8(float d[4], const uint32_t a[4], uint32_t b0, uint32_t b1) {
    asm volatile(
        "mma.sync.aligned.m16n8k8.row.col.f32.tf32.tf32.f32 "
        "{%0,%1,%2,%3}, {%4,%5,%6,%7}, {%8,%9}, {%0,%1,%2,%3};"
        : "+f"(d[0]), "+f"(d[1]), "+f"(d[2]), "+f"(d[3])
        : "r"(a[0]), "r"(a[1]), "r"(a[2]), "r"(a[3]), "r"(b0), "r"(b1));
}

__global__ void k_pe(const float* __restrict__ tab, const float* __restrict__ Wp,
                     const float* __restrict__ bp) {
    __shared__ float ue[E];
    int b = blockIdx.x;
    int t = threadIdx.x;
    int uid = g_uid[b];
    if (t < E) ue[t] = tab[(size_t)uid * E + t];
    __syncthreads();
    float acc = bp[t];
#pragma unroll
    for (int e = 0; e < E; e++) acc += ue[e] * Wp[e * P + t];
    g_pe[b * P + t] = acc;
}

// --- q = concat(x, pe) @ Wq[sid] via mma.sync tf32 (R6 version, 173us) ---
__global__ __launch_bounds__(256) void k_qgemm(const float* __restrict__ x,
                                               const float* __restrict__ Wq) {
    __shared__ float Ash[64][36], Asl[64][36];
    __shared__ float Bsh[32][68], Bsl[32][68];
    int b = blockIdx.z;
    int n0 = blockIdx.x * 64, m0 = blockIdx.y * 64;
    int sid = ((unsigned)g_uid[b]) % NSHARD;
    const float* Wg = Wq + (size_t)sid * IND * QO;
    int tid = threadIdx.x;
    int lane = tid & 31, warp = tid >> 5;
    int g = lane >> 2, c = lane & 3;
    int wm = warp & 3, wn = warp >> 2;
    const float* xb = x + ((size_t)b * SS + m0) * INSZ;
    const float* pe = g_pe + b * P;

    float d[4][4];
#pragma unroll
    for (int i = 0; i < 4; i++)
#pragma unroll
        for (int j = 0; j < 4; j++) d[i][j] = 0.f;

    for (int k0 = 0; k0 < IND; k0 += 32) {
        for (int i = tid; i < 64 * 8; i += 256) {
            int row = i >> 3, k4 = (i & 7) * 4;
            float4 v;
            if (k0 < INSZ) v = *(const float4*)&xb[row * INSZ + k0 + k4];
            else v = *(const float4*)&pe[k0 - INSZ + k4];
            uint32_t hx, lx, hy, ly, hz, lz, hw, lw;
            spl(v.x, hx, lx); spl(v.y, hy, ly); spl(v.z, hz, lz); spl(v.w, hw, lw);
            Ash[row][k4] = __uint_as_float(hx); Ash[row][k4 + 1] = __uint_as_float(hy);
            Ash[row][k4 + 2] = __uint_as_float(hz); Ash[row][k4 + 3] = __uint_as_float(hw);
            Asl[row][k4] = __uint_as_float(lx); Asl[row][k4 + 1] = __uint_as_float(ly);
            Asl[row][k4 + 2] = __uint_as_float(lz); Asl[row][k4 + 3] = __uint_as_float(lw);
        }
        for (int i = tid; i < 32 * 16; i += 256) {
            int kk = i >> 4, n4 = (i & 15) * 4;
            float4 v = *(const float4*)&Wg[(size_t)(k0 + kk) * QO + n0 + n4];
            uint32_t hx, lx, hy, ly, hz, lz, hw, lw;
            spl(v.x, hx, lx); spl(v.y, hy, ly); spl(v.z, hz, lz); spl(v.w, hw, lw);
            Bsh[kk][n4] = __uint_as_float(hx); Bsh[kk][n4 + 1] = __uint_as_float(hy);
            Bsh[kk][n4 + 2] = __uint_as_float(hz); Bsh[kk][n4 + 3] = __uint_as_float(hw);
            Bsl[kk][n4] = __uint_as_float(lx); Bsl[kk][n4 + 1] = __uint_as_float(ly);
            Bsl[kk][n4 + 2] = __uint_as_float(lz); Bsl[kk][n4 + 3] = __uint_as_float(lw);
        }
        __syncthreads();
#pragma unroll
        for (int ks = 0; ks < 4; ks++) {
            uint32_t ah[4], al[4];
            ah[0] = __float_as_uint(Ash[wm * 16 + g][ks * 8 + c]);
            ah[1] = __float_as_uint(Ash[wm * 16 + g + 8][ks * 8 + c]);
            ah[2] = __float_as_uint(Ash[wm * 16 + g][ks * 8 + c + 4]);
            ah[3] = __float_as_uint(Ash[wm * 16 + g + 8][ks * 8 + c + 4]);
            al[0] = __float_as_uint(Asl[wm * 16 + g][ks * 8 + c]);
            al[1] = __float_as_uint(Asl[wm * 16 + g + 8][ks * 8 + c]);
            al[2] = __float_as_uint(Asl[wm * 16 + g][ks * 8 + c + 4]);
            al[3] = __float_as_uint(Asl[wm * 16 + g + 8][ks * 8 + c + 4]);
#pragma unroll
            for (int nt = 0; nt < 4; nt++) {
                int nn = wn * 32 + nt * 8;
                uint32_t bh0 = __float_as_uint(Bsh[ks * 8 + c][nn + g]);
                uint32_t bh1 = __float_as_uint(Bsh[ks * 8 + c + 4][nn + g]);
                uint32_t bl0 = __float_as_uint(Bsl[ks * 8 + c][nn + g]);
                uint32_t bl1 = __float_as_uint(Bsl[ks * 8 + c + 4][nn + g]);
                mma8(d[nt], ah, bh0, bh1);
                mma8(d[nt], ah, bl0, bl1);
                mma8(d[nt], al, bh0, bh1);
            }
        }
        __syncthreads();
    }
    float* qb = g_q + ((size_t)b * SS + m0) * QO + n0;
#pragma unroll
    for (int nt = 0; nt < 4; nt++) {
        int nn = wn * 32 + nt * 8 + 2 * c;
        float2 v01 = {d[nt][0], d[nt][1]};
        float2 v23 = {d[nt][2], d[nt][3]};
        *(float2*)&qb[(size_t)(wm * 16 + g) * QO + nn] = v01;
        *(float2*)&qb[(size_t)(wm * 16 + g + 8) * QO + nn] = v23;
    }
}

// ---------------- fused attention: R4 structure, occ 2, 2-pass phase 2 ----------------
// block = (b, 8 s-positions) = 32 rows. grid (16, B), 256 threads, 2 CTA/SM.
__global__ __launch_bounds__(256, 2) void k_attn(const float* __restrict__ mem,
                                                 float* __restrict__ out) {
    extern __shared__ float sm[];
    float* sc = sm;               // [32][516]
    float* ms = sc + 32 * SCP;    // [128][68]
    float* qs = ms + 128 * MSP;   // [32][68]

    int tid = threadIdx.x;
    int lane = tid & 31, warp = tid >> 5;
    int g = lane >> 2, c = lane & 3;
    int rt = warp >> 2;
    int wq = warp & 3;
    int b = blockIdx.y;
    int s0 = blockIdx.x * 8;
    int sid = ((unsigned)g_uid[b]) % NSHARD;
    const float* M = mem + (size_t)sid * MSZ * WD;

    const float* qsrc = g_q + ((size_t)b * SS + s0) * QO;
    for (int i = tid; i < 32 * 16; i += 256) {
        int row = i >> 4, w4 = (i & 15) * 4;
        float4 v = *(const float4*)&qsrc[(size_t)(row >> 2) * QO + (row & 3) * WD + w4];
        *(float4*)&qs[row * MSP + w4] = v;
    }

    uint32_t ah[8][4], al[8][4];

    // ---- phase 1: scores[32,512] ----
    for (int ch = 0; ch < 4; ch++) {
        for (int i = tid; i < 128 * 16; i += 256) {
            int m = i >> 4, w4 = (i & 15) * 4;
            *(float4*)&ms[m * MSP + w4] = *(const float4*)&M[(size_t)(ch * 128 + m) * WD + w4];
        }
        __syncthreads();
        if (ch == 0) {
#pragma unroll
            for (int k = 0; k < 8; k++) {
                float a0 = qs[(rt * 16 + g) * MSP + k * 8 + c];
                float a1 = qs[(rt * 16 + g + 8) * MSP + k * 8 + c];
                float a2 = qs[(rt * 16 + g) * MSP + k * 8 + c + 4];
                float a3 = qs[(rt * 16 + g + 8) * MSP + k * 8 + c + 4];
                spl(a0, ah[k][0], al[k][0]);
                spl(a1, ah[k][1], al[k][1]);
                spl(a2, ah[k][2], al[k][2]);
                spl(a3, ah[k][3], al[k][3]);
            }
        }
#pragma unroll
        for (int nt = 0; nt < 4; nt++) {
            int n0 = wq * 32 + nt * 8;
            float d[4] = {0.f, 0.f, 0.f, 0.f};
#pragma unroll
            for (int k = 0; k < 8; k++) {
                float b0f = ms[(n0 + g) * MSP + k * 8 + c];
                float b1f = ms[(n0 + g) * MSP + k * 8 + c + 4];
                uint32_t bh0, bl0, bh1, bl1;
                spl(b0f, bh0, bl0);
                spl(b1f, bh1, bl1);
                mma8(d, ah[k], bh0, bh1);
                mma8(d, ah[k], bl0, bl1);
                mma8(d, al[k], bh0, bh1);
            }
            int mg = ch * 128 + n0 + 2 * c;
            float2 v01 = {d[0], d[1]};
            float2 v23 = {d[2], d[3]};
            *(float2*)&sc[(rt * 16 + g) * SCP + mg] = v01;
            *(float2*)&sc[(rt * 16 + g + 8) * SCP + mg] = v23;
        }
        __syncthreads();
    }

    // ---- softmax ----
    for (int rr = 0; rr < 4; rr++) {
        int row = warp * 4 + rr;
        float* srow = sc + row * SCP;
        float vals[16];
        float mx = -1e30f;
#pragma unroll
        for (int j = 0; j < 16; j++) {
            vals[j] = srow[lane + 32 * j];
            mx = fmaxf(mx, vals[j]);
        }
#pragma unroll
        for (int o = 16; o > 0; o >>= 1) mx = fmaxf(mx, __shfl_xor_sync(0xffffffffu, mx, o));
        float sum = 0.f;
#pragma unroll
        for (int j = 0; j < 16; j++) {
            vals[j] = __expf(vals[j] - mx);
            sum += vals[j];
        }
#pragma unroll
        for (int o = 16; o > 0; o >>= 1) sum += __shfl_xor_sync(0xffffffffu, sum, o);
        float inv = 1.f / sum;
#pragma unroll
        for (int j = 0; j < 16; j++) srow[lane + 32 * j] = vals[j] * inv;
        if (b == BB - 1) {
            float* fs = out + (size_t)BB * SS * RR * WD + (size_t)(s0 * 4 + row) * MSZ;
#pragma unroll
            for (int j = 0; j < 16; j++) fs[lane + 32 * j] = vals[j] * inv;
        }
    }

    // ---- phase 2: read = wts @ mem, 2-pass tf32 ----
    float acc[2][4];
#pragma unroll
    for (int nt = 0; nt < 2; nt++)
#pragma unroll
        for (int j = 0; j < 4; j++) acc[nt][j] = 0.f;

    for (int ch = 0; ch < 4; ch++) {
        __syncthreads();
        for (int i = tid; i < 128 * 16; i += 256) {
            int m = i >> 4, w4 = (i & 15) * 4;
            *(float4*)&ms[m * MSP + w4] = *(const float4*)&M[(size_t)(ch * 128 + m) * WD + w4];
        }
        __syncthreads();
#pragma unroll
        for (int kt = 0; kt < 16; kt++) {
            int kg = ch * 128 + kt * 8;
            uint32_t wh[4];
            wh[0] = t32(sc[(rt * 16 + g) * SCP + kg + c]);
            wh[1] = t32(sc[(rt * 16 + g + 8) * SCP + kg + c]);
            wh[2] = t32(sc[(rt * 16 + g) * SCP + kg + c + 4]);
            wh[3] = t32(sc[(rt * 16 + g + 8) * SCP + kg + c + 4]);
#pragma unroll
            for (int nt = 0; nt < 2; nt++) {
                int n0 = wq * 16 + nt * 8;
                float b0f = ms[(kt * 8 + c) * MSP + n0 + g];
                float b1f = ms[(kt * 8 + c + 4) * MSP + n0 + g];
                uint32_t bh0, bl0, bh1, bl1;
                spl(b0f, bh0, bl0);
                spl(b1f, bh1, bl1);
                mma8(acc[nt], wh, bh0, bh1);
                mma8(acc[nt], wh, bl0, bl1);
            }
        }
    }

    float* ob = out + ((size_t)b * 512 + s0 * 4) * WD;
#pragma unroll
    for (int nt = 0; nt < 2; nt++) {
        int wcol = wq * 16 + nt * 8 + 2 * c;
        float2 v01 = {acc[nt][0], acc[nt][1]};
        float2 v23 = {acc[nt][2], acc[nt][3]};
        *(float2*)&ob[(size_t)(rt * 16 + g) * WD + wcol] = v01;
        *(float2*)&ob[(size_t)(rt * 16 + g + 8) * WD + wcol] = v23;
    }
}

extern "C" void kernel_launch(void* const* d_in, const int* in_sizes, int n_in,
                              void* d_out, int out_size) {
    const float* x = (const float*)d_in[0];
    const int* uid = (const int*)d_in[1];
    const float* tab = (const float*)d_in[2];
    const float* Wp = (const float*)d_in[3];
    const float* bp = (const float*)d_in[4];
    const float* Wq = (const float*)d_in[5];
    const float* memp = (const float*)d_in[6];
    float* out = (float*)d_out;

    k_uid<<<1, 256>>>(uid);
    k_pe<<<BB, 128>>>(tab, Wp, bp);
    dim3 g2(4, 2, BB);
    k_qgemm<<<g2, 256>>>(x, Wq);

    const int smem_bytes = (32 * SCP + 128 * MSP + 32 * MSP) * 4;
    cudaFuncSetAttribute(k_attn, cudaFuncAttributeMaxDynamicSharedMemorySize, smem_bytes);
    dim3 g3(16, BB);
    k_attn<<<g3, 256, smem_bytes>>>(memp, out);
}

// round 8
// speedup vs baseline: 1.5201x; 1.1408x over previous
#include <cuda_runtime.h>
#include <cstdint>

#define NUSERS 100000
#define E 64
#define P 128
#define NSHARD 16
#define MSZ 512
#define WD 64
#define RR 4
#define INSZ 256
#define BB 256
#define SS 128
#define IND 384
#define QO 256

#define SCP 516
#define MSP 68

__device__ float g_pe[BB * P];
__device__ float g_q[(size_t)BB * SS * QO];
__device__ int g_uid[BB];

__global__ void k_uid(const int* __restrict__ u) {
    int s = 2;
#pragma unroll
    for (int i = 0; i < 8; i++)
        if (u[2 * i + 1] != 0) s = 1;
    int b = blockIdx.x * blockDim.x + threadIdx.x;
    if (b < BB) g_uid[b] = u[b * s];
}

// exact hi/lo split: hi = truncate-to-tf32 (mask), lo = exact remainder.
// HMMA tf32 reads only the top 19 bits of each f32 operand, so lo needs no cvt.
__device__ __forceinline__ void msp(float x, uint32_t& h, uint32_t& l) {
    h = __float_as_uint(x) & 0xFFFFE000u;
    l = __float_as_uint(x - __uint_as_float(h));
}
__device__ __forceinline__ void mma8(float d[4], const uint32_t a[4], uint32_t b0, uint32_t b1) {
    asm volatile(
        "mma.sync.aligned.m16n8k8.row.col.f32.tf32.tf32.f32 "
        "{%0,%1,%2,%3}, {%4,%5,%6,%7}, {%8,%9}, {%0,%1,%2,%3};"
        : "+f"(d[0]), "+f"(d[1]), "+f"(d[2]), "+f"(d[3])
        : "r"(a[0]), "r"(a[1]), "r"(a[2]), "r"(a[3]), "r"(b0), "r"(b1));
}

__global__ void k_pe(const float* __restrict__ tab, const float* __restrict__ Wp,
                     const float* __restrict__ bp) {
    __shared__ float ue[E];
    int b = blockIdx.x;
    int t = threadIdx.x;
    int uid = g_uid[b];
    if (t < E) ue[t] = tab[(size_t)uid * E + t];
    __syncthreads();
    float acc = bp[t];
#pragma unroll
    for (int e = 0; e < E; e++) acc += ue[e] * Wp[e * P + t];
    g_pe[b * P + t] = acc;
}

// --- q = concat(x, pe) @ Wq[sid] via mma.sync tf32, mask hi/lo, 3-pass ---
__global__ __launch_bounds__(256) void k_qgemm(const float* __restrict__ x,
                                               const float* __restrict__ Wq) {
    __shared__ float Ash[64][36], Asl[64][36];
    __shared__ float Bsh[32][68], Bsl[32][68];
    int b = blockIdx.z;
    int n0 = blockIdx.x * 64, m0 = blockIdx.y * 64;
    int sid = ((unsigned)g_uid[b]) % NSHARD;
    const float* Wg = Wq + (size_t)sid * IND * QO;
    int tid = threadIdx.x;
    int lane = tid & 31, warp = tid >> 5;
    int g = lane >> 2, c = lane & 3;
    int wm = warp & 3, wn = warp >> 2;
    const float* xb = x + ((size_t)b * SS + m0) * INSZ;
    const float* pe = g_pe + b * P;

    float d[4][4];
#pragma unroll
    for (int i = 0; i < 4; i++)
#pragma unroll
        for (int j = 0; j < 4; j++) d[i][j] = 0.f;

    for (int k0 = 0; k0 < IND; k0 += 32) {
        for (int i = tid; i < 64 * 8; i += 256) {
            int row = i >> 3, k4 = (i & 7) * 4;
            float4 v;
            if (k0 < INSZ) v = *(const float4*)&xb[row * INSZ + k0 + k4];
            else v = *(const float4*)&pe[k0 - INSZ + k4];
            uint32_t hx, lx, hy, ly, hz, lz, hw, lw;
            msp(v.x, hx, lx); msp(v.y, hy, ly); msp(v.z, hz, lz); msp(v.w, hw, lw);
            Ash[row][k4] = __uint_as_float(hx); Ash[row][k4 + 1] = __uint_as_float(hy);
            Ash[row][k4 + 2] = __uint_as_float(hz); Ash[row][k4 + 3] = __uint_as_float(hw);
            Asl[row][k4] = __uint_as_float(lx); Asl[row][k4 + 1] = __uint_as_float(ly);
            Asl[row][k4 + 2] = __uint_as_float(lz); Asl[row][k4 + 3] = __uint_as_float(lw);
        }
        for (int i = tid; i < 32 * 16; i += 256) {
            int kk = i >> 4, n4 = (i & 15) * 4;
            float4 v = *(const float4*)&Wg[(size_t)(k0 + kk) * QO + n0 + n4];
            uint32_t hx, lx, hy, ly, hz, lz, hw, lw;
            msp(v.x, hx, lx); msp(v.y, hy, ly); msp(v.z, hz, lz); msp(v.w, hw, lw);
            Bsh[kk][n4] = __uint_as_float(hx); Bsh[kk][n4 + 1] = __uint_as_float(hy);
            Bsh[kk][n4 + 2] = __uint_as_float(hz); Bsh[kk][n4 + 3] = __uint_as_float(hw);
            Bsl[kk][n4] = __uint_as_float(lx); Bsl[kk][n4 + 1] = __uint_as_float(ly);
            Bsl[kk][n4 + 2] = __uint_as_float(lz); Bsl[kk][n4 + 3] = __uint_as_float(lw);
        }
        __syncthreads();
#pragma unroll
        for (int ks = 0; ks < 4; ks++) {
            uint32_t ah[4], al[4];
            ah[0] = __float_as_uint(Ash[wm * 16 + g][ks * 8 + c]);
            ah[1] = __float_as_uint(Ash[wm * 16 + g + 8][ks * 8 + c]);
            ah[2] = __float_as_uint(Ash[wm * 16 + g][ks * 8 + c + 4]);
            ah[3] = __float_as_uint(Ash[wm * 16 + g + 8][ks * 8 + c + 4]);
            al[0] = __float_as_uint(Asl[wm * 16 + g][ks * 8 + c]);
            al[1] = __float_as_uint(Asl[wm * 16 + g + 8][ks * 8 + c]);
            al[2] = __float_as_uint(Asl[wm * 16 + g][ks * 8 + c + 4]);
            al[3] = __float_as_uint(Asl[wm * 16 + g + 8][ks * 8 + c + 4]);
#pragma unroll
            for (int nt = 0; nt < 4; nt++) {
                int nn = wn * 32 + nt * 8;
                uint32_t bh0 = __float_as_uint(Bsh[ks * 8 + c][nn + g]);
                uint32_t bh1 = __float_as_uint(Bsh[ks * 8 + c + 4][nn + g]);
                uint32_t bl0 = __float_as_uint(Bsl[ks * 8 + c][nn + g]);
                uint32_t bl1 = __float_as_uint(Bsl[ks * 8 + c + 4][nn + g]);
                mma8(d[nt], ah, bh0, bh1);
                mma8(d[nt], ah, bl0, bl1);
                mma8(d[nt], al, bh0, bh1);
            }
        }
        __syncthreads();
    }
    float* qb = g_q + ((size_t)b * SS + m0) * QO + n0;
#pragma unroll
    for (int nt = 0; nt < 4; nt++) {
        int nn = wn * 32 + nt * 8 + 2 * c;
        float2 v01 = {d[nt][0], d[nt][1]};
        float2 v23 = {d[nt][2], d[nt][3]};
        *(float2*)&qb[(size_t)(wm * 16 + g) * QO + nn] = v01;
        *(float2*)&qb[(size_t)(wm * 16 + g + 8) * QO + nn] = v23;
    }
}

// ---------------- fused attention: mask splits, no cvt in hot loops ----------------
__global__ __launch_bounds__(256, 2) void k_attn(const float* __restrict__ mem,
                                                 float* __restrict__ out) {
    extern __shared__ float sm[];
    float* sc = sm;               // [32][516]
    float* ms = sc + 32 * SCP;    // [128][68]
    float* qs = ms + 128 * MSP;   // [32][68]

    int tid = threadIdx.x;
    int lane = tid & 31, warp = tid >> 5;
    int g = lane >> 2, c = lane & 3;
    int rt = warp >> 2;
    int wq = warp & 3;
    int b = blockIdx.y;
    int s0 = blockIdx.x * 8;
    int sid = ((unsigned)g_uid[b]) % NSHARD;
    const float* M = mem + (size_t)sid * MSZ * WD;

    const float* qsrc = g_q + ((size_t)b * SS + s0) * QO;
    for (int i = tid; i < 32 * 16; i += 256) {
        int row = i >> 4, w4 = (i & 15) * 4;
        float4 v = *(const float4*)&qsrc[(size_t)(row >> 2) * QO + (row & 3) * WD + w4];
        *(float4*)&qs[row * MSP + w4] = v;
    }

    uint32_t ah[8][4], al[8][4];

    // ---- phase 1: scores[32,512] ----
    for (int ch = 0; ch < 4; ch++) {
        for (int i = tid; i < 128 * 16; i += 256) {
            int m = i >> 4, w4 = (i & 15) * 4;
            *(float4*)&ms[m * MSP + w4] = *(const float4*)&M[(size_t)(ch * 128 + m) * WD + w4];
        }
        __syncthreads();
        if (ch == 0) {
#pragma unroll
            for (int k = 0; k < 8; k++) {
                msp(qs[(rt * 16 + g) * MSP + k * 8 + c], ah[k][0], al[k][0]);
                msp(qs[(rt * 16 + g + 8) * MSP + k * 8 + c], ah[k][1], al[k][1]);
                msp(qs[(rt * 16 + g) * MSP + k * 8 + c + 4], ah[k][2], al[k][2]);
                msp(qs[(rt * 16 + g + 8) * MSP + k * 8 + c + 4], ah[k][3], al[k][3]);
            }
        }
#pragma unroll
        for (int nt = 0; nt < 4; nt++) {
            int n0 = wq * 32 + nt * 8;
            float d[4] = {0.f, 0.f, 0.f, 0.f};
#pragma unroll
            for (int k = 0; k < 8; k++) {
                uint32_t bh0, bl0, bh1, bl1;
                msp(ms[(n0 + g) * MSP + k * 8 + c], bh0, bl0);
                msp(ms[(n0 + g) * MSP + k * 8 + c + 4], bh1, bl1);
                mma8(d, ah[k], bh0, bh1);
                mma8(d, ah[k], bl0, bl1);
                mma8(d, al[k], bh0, bh1);
            }
            int mg = ch * 128 + n0 + 2 * c;
            float2 v01 = {d[0], d[1]};
            float2 v23 = {d[2], d[3]};
            *(float2*)&sc[(rt * 16 + g) * SCP + mg] = v01;
            *(float2*)&sc[(rt * 16 + g + 8) * SCP + mg] = v23;
        }
        __syncthreads();
    }

    // ---- softmax ----
    for (int rr = 0; rr < 4; rr++) {
        int row = warp * 4 + rr;
        float* srow = sc + row * SCP;
        float vals[16];
        float mx = -1e30f;
#pragma unroll
        for (int j = 0; j < 16; j++) {
            vals[j] = srow[lane + 32 * j];
            mx = fmaxf(mx, vals[j]);
        }
#pragma unroll
        for (int o = 16; o > 0; o >>= 1) mx = fmaxf(mx, __shfl_xor_sync(0xffffffffu, mx, o));
        float sum = 0.f;
#pragma unroll
        for (int j = 0; j < 16; j++) {
            vals[j] = __expf(vals[j] - mx);
            sum += vals[j];
        }
#pragma unroll
        for (int o = 16; o > 0; o >>= 1) sum += __shfl_xor_sync(0xffffffffu, sum, o);
        float inv = 1.f / sum;
#pragma unroll
        for (int j = 0; j < 16; j++) srow[lane + 32 * j] = vals[j] * inv;
        if (b == BB - 1) {
            float* fs = out + (size_t)BB * SS * RR * WD + (size_t)(s0 * 4 + row) * MSZ;
#pragma unroll
            for (int j = 0; j < 16; j++) fs[lane + 32 * j] = vals[j] * inv;
        }
    }

    // ---- phase 2: read = wts @ mem, 2-pass, raw-f32 weights ----
    float acc[2][4];
#pragma unroll
    for (int nt = 0; nt < 2; nt++)
#pragma unroll
        for (int j = 0; j < 4; j++) acc[nt][j] = 0.f;

    for (int ch = 0; ch < 4; ch++) {
        __syncthreads();
        for (int i = tid; i < 128 * 16; i += 256) {
            int m = i >> 4, w4 = (i & 15) * 4;
            *(float4*)&ms[m * MSP + w4] = *(const float4*)&M[(size_t)(ch * 128 + m) * WD + w4];
        }
        __syncthreads();
#pragma unroll
        for (int kt = 0; kt < 16; kt++) {
            int kg = ch * 128 + kt * 8;
            uint32_t wh[4];
            wh[0] = __float_as_uint(sc[(rt * 16 + g) * SCP + kg + c]);
            wh[1] = __float_as_uint(sc[(rt * 16 + g + 8) * SCP + kg + c]);
            wh[2] = __float_as_uint(sc[(rt * 16 + g) * SCP + kg + c + 4]);
            wh[3] = __float_as_uint(sc[(rt * 16 + g + 8) * SCP + kg + c + 4]);
#pragma unroll
            for (int nt = 0; nt < 2; nt++) {
                int n0 = wq * 16 + nt * 8;
                uint32_t bh0, bl0, bh1, bl1;
                msp(ms[(kt * 8 + c) * MSP + n0 + g], bh0, bl0);
                msp(ms[(kt * 8 + c + 4) * MSP + n0 + g], bh1, bl1);
                mma8(acc[nt], wh, bh0, bh1);
                mma8(acc[nt], wh, bl0, bl1);
            }
        }
    }

    float* ob = out + ((size_t)b * 512 + s0 * 4) * WD;
#pragma unroll
    for (int nt = 0; nt < 2; nt++) {
        int wcol = wq * 16 + nt * 8 + 2 * c;
        float2 v01 = {acc[nt][0], acc[nt][1]};
        float2 v23 = {acc[nt][2], acc[nt][3]};
        *(float2*)&ob[(size_t)(rt * 16 + g) * WD + wcol] = v01;
        *(float2*)&ob[(size_t)(rt * 16 + g + 8) * WD + wcol] = v23;
    }
}

extern "C" void kernel_launch(void* const* d_in, const int* in_sizes, int n_in,
                              void* d_out, int out_size) {
    const float* x = (const float*)d_in[0];
    const int* uid = (const int*)d_in[1];
    const float* tab = (const float*)d_in[2];
    const float* Wp = (const float*)d_in[3];
    const float* bp = (const float*)d_in[4];
    const float* Wq = (const float*)d_in[5];
    const float* memp = (const float*)d_in[6];
    float* out = (float*)d_out;

    k_uid<<<1, 256>>>(uid);
    k_pe<<<BB, 128>>>(tab, Wp, bp);
    dim3 g2(4, 2, BB);
    k_qgemm<<<g2, 256>>>(x, Wq);

    const int smem_bytes = (32 * SCP + 128 * MSP + 32 * MSP) * 4;
    cudaFuncSetAttribute(k_attn, cudaFuncAttributeMaxDynamicSharedMemorySize, smem_bytes);
    dim3 g3(16, BB);
    k_attn<<<g3, 256, smem_bytes>>>(memp, out);
}

// round 9
// speedup vs baseline: 1.8829x; 1.2386x over previous
#include <cuda_runtime.h>
#include <cstdint>

#define NUSERS 100000
#define E 64
#define P 128
#define NSHARD 16
#define MSZ 512
#define WD 64
#define RR 4
#define INSZ 256
#define BB 256
#define SS 128
#define IND 384
#define QO 256

#define MSP 68
#define ESP 20

__device__ float g_pe[BB * P];
__device__ float g_q[(size_t)BB * SS * QO];
__device__ int g_uid[BB];

__global__ void k_uid(const int* __restrict__ u) {
    int s = 2;
#pragma unroll
    for (int i = 0; i < 8; i++)
        if (u[2 * i + 1] != 0) s = 1;
    int b = blockIdx.x * blockDim.x + threadIdx.x;
    if (b < BB) g_uid[b] = u[b * s];
}

// exact hi/lo split: hi = tf32-truncate via mask, lo = exact remainder (HMMA reads top 19 bits)
__device__ __forceinline__ void msp(float x, uint32_t& h, uint32_t& l) {
    h = __float_as_uint(x) & 0xFFFFE000u;
    l = __float_as_uint(x - __uint_as_float(h));
}
__device__ __forceinline__ void mma8(float d[4], const uint32_t a[4], uint32_t b0, uint32_t b1) {
    asm volatile(
        "mma.sync.aligned.m16n8k8.row.col.f32.tf32.tf32.f32 "
        "{%0,%1,%2,%3}, {%4,%5,%6,%7}, {%8,%9}, {%0,%1,%2,%3};"
        : "+f"(d[0]), "+f"(d[1]), "+f"(d[2]), "+f"(d[3])
        : "r"(a[0]), "r"(a[1]), "r"(a[2]), "r"(a[3]), "r"(b0), "r"(b1));
}

__global__ void k_pe(const float* __restrict__ tab, const float* __restrict__ Wp,
                     const float* __restrict__ bp) {
    __shared__ float ue[E];
    int b = blockIdx.x;
    int t = threadIdx.x;
    int uid = g_uid[b];
    if (t < E) ue[t] = tab[(size_t)uid * E + t];
    __syncthreads();
    float acc = bp[t];
#pragma unroll
    for (int e = 0; e < E; e++) acc += ue[e] * Wp[e * P + t];
    g_pe[b * P + t] = acc;
}

// --- q = concat(x, pe) @ Wq[sid]; raw staging, in-loop mask split, 3-pass ---
__global__ __launch_bounds__(256) void k_qgemm(const float* __restrict__ x,
                                               const float* __restrict__ Wq) {
    __shared__ float As[64][36];
    __shared__ float Bs[32][68];
    int b = blockIdx.z;
    int n0 = blockIdx.x * 64, m0 = blockIdx.y * 64;
    int sid = ((unsigned)g_uid[b]) % NSHARD;
    const float* Wg = Wq + (size_t)sid * IND * QO;
    int tid = threadIdx.x;
    int lane = tid & 31, warp = tid >> 5;
    int g = lane >> 2, c = lane & 3;
    int wm = warp & 3, wn = warp >> 2;
    const float* xb = x + ((size_t)b * SS + m0) * INSZ;
    const float* pe = g_pe + b * P;

    float d[4][4];
#pragma unroll
    for (int i = 0; i < 4; i++)
#pragma unroll
        for (int j = 0; j < 4; j++) d[i][j] = 0.f;

    for (int k0 = 0; k0 < IND; k0 += 32) {
        for (int i = tid; i < 64 * 8; i += 256) {
            int row = i >> 3, k4 = (i & 7) * 4;
            float4 v;
            if (k0 < INSZ) v = *(const float4*)&xb[row * INSZ + k0 + k4];
            else v = *(const float4*)&pe[k0 - INSZ + k4];
            *(float4*)&As[row][k4] = v;
        }
        for (int i = tid; i < 32 * 16; i += 256) {
            int kk = i >> 4, n4 = (i & 15) * 4;
            *(float4*)&Bs[kk][n4] = *(const float4*)&Wg[(size_t)(k0 + kk) * QO + n0 + n4];
        }
        __syncthreads();
#pragma unroll
        for (int ks = 0; ks < 4; ks++) {
            uint32_t ah[4], al[4];
            msp(As[wm * 16 + g][ks * 8 + c], ah[0], al[0]);
            msp(As[wm * 16 + g + 8][ks * 8 + c], ah[1], al[1]);
            msp(As[wm * 16 + g][ks * 8 + c + 4], ah[2], al[2]);
            msp(As[wm * 16 + g + 8][ks * 8 + c + 4], ah[3], al[3]);
#pragma unroll
            for (int nt = 0; nt < 4; nt++) {
                int nn = wn * 32 + nt * 8;
                uint32_t bh0, bl0, bh1, bl1;
                msp(Bs[ks * 8 + c][nn + g], bh0, bl0);
                msp(Bs[ks * 8 + c + 4][nn + g], bh1, bl1);
                mma8(d[nt], ah, bh0, bh1);
                mma8(d[nt], ah, bl0, bl1);
                mma8(d[nt], al, bh0, bh1);
            }
        }
        __syncthreads();
    }
    float* qb = g_q + ((size_t)b * SS + m0) * QO + n0;
#pragma unroll
    for (int nt = 0; nt < 4; nt++) {
        int nn = wn * 32 + nt * 8 + 2 * c;
        float2 v01 = {d[nt][0], d[nt][1]};
        float2 v23 = {d[nt][2], d[nt][3]};
        *(float2*)&qb[(size_t)(wm * 16 + g) * QO + nn] = v01;
        *(float2*)&qb[(size_t)(wm * 16 + g + 8) * QO + nn] = v23;
    }
}

// ---------------- flash-style fused attention ----------------
// block = 128 rows (32 s), 8 warps, warp owns 16 complete rows. grid (4, B).
__global__ __launch_bounds__(256, 2) void k_attn(const float* __restrict__ mem,
                                                 float* __restrict__ out) {
    extern __shared__ float sm[];
    float* qs = sm;                 // [128][68]
    float* ms = qs + 128 * MSP;     // [128][68]
    float* es = ms + 128 * MSP;     // 8 warps x [16][20]

    int tid = threadIdx.x;
    int lane = tid & 31, warp = tid >> 5;
    int g = lane >> 2, c = lane & 3;
    int b = blockIdx.y;
    int s0 = blockIdx.x * 32;
    int sid = ((unsigned)g_uid[b]) % NSHARD;
    const float* M = mem + (size_t)sid * MSZ * WD;
    float* ew = es + warp * (16 * ESP);
    int wrow = warp * 16;

    // stage q: qs[row][w], row = s_local*4 + r, 128 rows
    const float* qsrc = g_q + ((size_t)b * SS + s0) * QO;
    for (int i = tid; i < 128 * 16; i += 256) {
        int row = i >> 4, w4 = (i & 15) * 4;
        float4 v = *(const float4*)&qsrc[(size_t)(row >> 2) * QO + (row & 3) * WD + w4];
        *(float4*)&qs[row * MSP + w4] = v;
    }

    uint32_t ah[8][4], al[8][4];
    float acc[8][4];
#pragma unroll
    for (int nt = 0; nt < 8; nt++)
#pragma unroll
        for (int j = 0; j < 4; j++) acc[nt][j] = 0.f;
    float mx0 = -1e30f, mx1 = -1e30f, sm0 = 0.f, sm1 = 0.f;

    for (int ch = 0; ch < 4; ch++) {
        for (int i = tid; i < 128 * 16; i += 256) {
            int m = i >> 4, w4 = (i & 15) * 4;
            *(float4*)&ms[m * MSP + w4] = *(const float4*)&M[(size_t)(ch * 128 + m) * WD + w4];
        }
        __syncthreads();
        if (ch == 0) {
#pragma unroll
            for (int k = 0; k < 8; k++) {
                msp(qs[(wrow + g) * MSP + k * 8 + c], ah[k][0], al[k][0]);
                msp(qs[(wrow + g + 8) * MSP + k * 8 + c], ah[k][1], al[k][1]);
                msp(qs[(wrow + g) * MSP + k * 8 + c + 4], ah[k][2], al[k][2]);
                msp(qs[(wrow + g + 8) * MSP + k * 8 + c + 4], ah[k][3], al[k][3]);
            }
        }
        // 8 sub-blocks of 16 m-cols
        for (int sb = 0; sb < 8; sb++) {
            float e[2][4];
#pragma unroll
            for (int nt2 = 0; nt2 < 2; nt2++) {
                int mc = sb * 16 + nt2 * 8;
                float d[4] = {0.f, 0.f, 0.f, 0.f};
#pragma unroll
                for (int k = 0; k < 8; k++) {
                    uint32_t bh0, bl0, bh1, bl1;
                    msp(ms[(mc + g) * MSP + k * 8 + c], bh0, bl0);
                    msp(ms[(mc + g) * MSP + k * 8 + c + 4], bh1, bl1);
                    mma8(d, ah[k], bh0, bh1);
                    mma8(d, ah[k], bl0, bl1);
                    mma8(d, al[k], bh0, bh1);
                }
                e[nt2][0] = d[0]; e[nt2][1] = d[1]; e[nt2][2] = d[2]; e[nt2][3] = d[3];
            }
            // row max over sub-block
            float m0 = fmaxf(fmaxf(e[0][0], e[0][1]), fmaxf(e[1][0], e[1][1]));
            float m1 = fmaxf(fmaxf(e[0][2], e[0][3]), fmaxf(e[1][2], e[1][3]));
            m0 = fmaxf(m0, __shfl_xor_sync(0xffffffffu, m0, 1));
            m0 = fmaxf(m0, __shfl_xor_sync(0xffffffffu, m0, 2));
            m1 = fmaxf(m1, __shfl_xor_sync(0xffffffffu, m1, 1));
            m1 = fmaxf(m1, __shfl_xor_sync(0xffffffffu, m1, 2));
            float nm0 = fmaxf(mx0, m0), nm1 = fmaxf(mx1, m1);
            float sc0 = __expf(mx0 - nm0), sc1 = __expf(mx1 - nm1);
            sm0 *= sc0; sm1 *= sc1;
#pragma unroll
            for (int nt = 0; nt < 8; nt++) {
                acc[nt][0] *= sc0; acc[nt][1] *= sc0;
                acc[nt][2] *= sc1; acc[nt][3] *= sc1;
            }
            mx0 = nm0; mx1 = nm1;
#pragma unroll
            for (int nt2 = 0; nt2 < 2; nt2++) {
                float e0 = __expf(e[nt2][0] - nm0);
                float e1 = __expf(e[nt2][1] - nm0);
                float e2 = __expf(e[nt2][2] - nm1);
                float e3 = __expf(e[nt2][3] - nm1);
                sm0 += e0 + e1; sm1 += e2 + e3;
                int col = nt2 * 8 + 2 * c;
                float2 v01 = {e0, e1};
                float2 v23 = {e2, e3};
                *(float2*)&ew[g * ESP + col] = v01;
                *(float2*)&ew[(g + 8) * ESP + col] = v23;
            }
            __syncwarp();
            // phase 2: accumulate read over this sub-block's 16 m
#pragma unroll
            for (int kg = 0; kg < 2; kg++) {
                uint32_t a[4];
                a[0] = __float_as_uint(ew[g * ESP + kg * 8 + c]);
                a[1] = __float_as_uint(ew[(g + 8) * ESP + kg * 8 + c]);
                a[2] = __float_as_uint(ew[g * ESP + kg * 8 + c + 4]);
                a[3] = __float_as_uint(ew[(g + 8) * ESP + kg * 8 + c + 4]);
                int mr = sb * 16 + kg * 8;
#pragma unroll
                for (int nt = 0; nt < 8; nt++) {
                    int w0 = nt * 8;
                    uint32_t bh0, bl0, bh1, bl1;
                    msp(ms[(mr + c) * MSP + w0 + g], bh0, bl0);
                    msp(ms[(mr + c + 4) * MSP + w0 + g], bh1, bl1);
                    mma8(acc[nt], a, bh0, bh1);
                    mma8(acc[nt], a, bl0, bl1);
                }
            }
            __syncwarp();
        }
        __syncthreads();
    }

    // finalize: reduce partial sums across c-lanes, scale, write
    sm0 += __shfl_xor_sync(0xffffffffu, sm0, 1);
    sm0 += __shfl_xor_sync(0xffffffffu, sm0, 2);
    sm1 += __shfl_xor_sync(0xffffffffu, sm1, 1);
    sm1 += __shfl_xor_sync(0xffffffffu, sm1, 2);
    float inv0 = 1.f / sm0, inv1 = 1.f / sm1;
    float* ob = out + ((size_t)b * 512 + s0 * 4) * WD;
#pragma unroll
    for (int nt = 0; nt < 8; nt++) {
        int col = nt * 8 + 2 * c;
        float2 v01 = {acc[nt][0] * inv0, acc[nt][1] * inv0};
        float2 v23 = {acc[nt][2] * inv1, acc[nt][3] * inv1};
        *(float2*)&ob[(size_t)(wrow + g) * WD + col] = v01;
        *(float2*)&ob[(size_t)(wrow + g + 8) * WD + col] = v23;
    }
}

// --- final_state for b = B-1: scores + softmax, scalar (tiny) ---
__global__ void k_fs(const float* __restrict__ mem, float* __restrict__ out) {
    __shared__ float q4[4 * 64];
    __shared__ float scs[4 * 528];
    int s = blockIdx.x;
    int tid = threadIdx.x;
    int lane = tid & 31, warp = tid >> 5;
    int sid = ((unsigned)g_uid[BB - 1]) % NSHARD;
    const float* M = mem + (size_t)sid * MSZ * WD;
    const float* qsrc = g_q + ((size_t)(BB - 1) * SS + s) * QO;
    q4[tid] = qsrc[tid];  // 256 = 4 rows x 64
    __syncthreads();
    for (int p = tid; p < 4 * MSZ; p += 256) {
        int r = p >> 9, m = p & 511;
        const float* qr = q4 + r * 64;
        const float* mr = M + (size_t)m * WD;
        float acc = 0.f;
#pragma unroll
        for (int w4 = 0; w4 < 64; w4 += 4) {
            float4 qv = *(const float4*)&qr[w4];
            float4 mv = *(const float4*)&mr[w4];
            acc += qv.x * mv.x + qv.y * mv.y + qv.z * mv.z + qv.w * mv.w;
        }
        scs[r * 528 + m] = acc;
    }
    __syncthreads();
    if (warp < 4) {
        int r = warp;
        float* srow = scs + r * 528;
        float vals[16];
        float mx = -1e30f;
#pragma unroll
        for (int j = 0; j < 16; j++) {
            vals[j] = srow[lane + 32 * j];
            mx = fmaxf(mx, vals[j]);
        }
#pragma unroll
        for (int o = 16; o > 0; o >>= 1) mx = fmaxf(mx, __shfl_xor_sync(0xffffffffu, mx, o));
        float sum = 0.f;
#pragma unroll
        for (int j = 0; j < 16; j++) {
            vals[j] = __expf(vals[j] - mx);
            sum += vals[j];
        }
#pragma unroll
        for (int o = 16; o > 0; o >>= 1) sum += __shfl_xor_sync(0xffffffffu, sum, o);
        float inv = 1.f / sum;
        float* fs = out + (size_t)BB * SS * RR * WD + (size_t)(s * 4 + r) * MSZ;
#pragma unroll
        for (int j = 0; j < 16; j++) fs[lane + 32 * j] = vals[j] * inv;
    }
}

extern "C" void kernel_launch(void* const* d_in, const int* in_sizes, int n_in,
                              void* d_out, int out_size) {
    const float* x = (const float*)d_in[0];
    const int* uid = (const int*)d_in[1];
    const float* tab = (const float*)d_in[2];
    const float* Wp = (const float*)d_in[3];
    const float* bp = (const float*)d_in[4];
    const float* Wq = (const float*)d_in[5];
    const float* memp = (const float*)d_in[6];
    float* out = (float*)d_out;

    k_uid<<<1, 256>>>(uid);
    k_pe<<<BB, 128>>>(tab, Wp, bp);
    dim3 g2(4, 2, BB);
    k_qgemm<<<g2, 256>>>(x, Wq);
    k_fs<<<SS, 256>>>(memp, out);

    const int smem_bytes = (2 * 128 * MSP + 8 * 16 * ESP) * 4;
    cudaFuncSetAttribute(k_attn, cudaFuncAttributeMaxDynamicSharedMemorySize, smem_bytes);
    dim3 g3(4, BB);
    k_attn<<<g3, 256, smem_bytes>>>(memp, out);
}

// round 10
// speedup vs baseline: 1.9127x; 1.0159x over previous
#include <cuda_runtime.h>
#include <cstdint>

#define NUSERS 100000
#define E 64
#define P 128
#define NSHARD 16
#define MSZ 512
#define WD 64
#define RR 4
#define INSZ 256
#define BB 256
#define SS 128
#define IND 384
#define QO 256

#define MSP 68
#define ESP 20

__device__ float g_pe[BB * P];
__device__ float g_q[(size_t)BB * SS * QO];
__device__ int g_uid[BB];

__global__ void k_uid(const int* __restrict__ u) {
    int s = 2;
#pragma unroll
    for (int i = 0; i < 8; i++)
        if (u[2 * i + 1] != 0) s = 1;
    int b = blockIdx.x * blockDim.x + threadIdx.x;
    if (b < BB) g_uid[b] = u[b * s];
}

__device__ __forceinline__ void msp(float x, uint32_t& h, uint32_t& l) {
    h = __float_as_uint(x) & 0xFFFFE000u;
    l = __float_as_uint(x - __uint_as_float(h));
}
__device__ __forceinline__ void mma8(float d[4], const uint32_t a[4], uint32_t b0, uint32_t b1) {
    asm volatile(
        "mma.sync.aligned.m16n8k8.row.col.f32.tf32.tf32.f32 "
        "{%0,%1,%2,%3}, {%4,%5,%6,%7}, {%8,%9}, {%0,%1,%2,%3};"
        : "+f"(d[0]), "+f"(d[1]), "+f"(d[2]), "+f"(d[3])
        : "r"(a[0]), "r"(a[1]), "r"(a[2]), "r"(a[3]), "r"(b0), "r"(b1));
}
__device__ __forceinline__ uint32_t smem_u32(const void* p) {
    uint32_t a;
    asm("{ .reg .u64 t; cvta.to.shared.u64 t, %1; cvt.u32.u64 %0, t; }" : "=r"(a) : "l"(p));
    return a;
}
__device__ __forceinline__ void cpa16(uint32_t s, const void* g) {
    asm volatile("cp.async.ca.shared.global [%0], [%1], 16;" :: "r"(s), "l"(g));
}
__device__ __forceinline__ void cpcommit() { asm volatile("cp.async.commit_group;"); }
__device__ __forceinline__ void cpwait1() { asm volatile("cp.async.wait_group 1;"); }
__device__ __forceinline__ void cpwait0() { asm volatile("cp.async.wait_group 0;"); }

__global__ void k_pe(const float* __restrict__ tab, const float* __restrict__ Wp,
                     const float* __restrict__ bp) {
    __shared__ float ue[E];
    int b = blockIdx.x;
    int t = threadIdx.x;
    int uid = g_uid[b];
    if (t < E) ue[t] = tab[(size_t)uid * E + t];
    __syncthreads();
    float acc = bp[t];
#pragma unroll
    for (int e = 0; e < E; e++) acc += ue[e] * Wp[e * P + t];
    g_pe[b * P + t] = acc;
}

// --- q = concat(x, pe) @ Wq[sid]; cp.async double-buffered, mask split, 3-pass ---
__global__ __launch_bounds__(256) void k_qgemm(const float* __restrict__ x,
                                               const float* __restrict__ Wq) {
    __shared__ float As[2][64][36];
    __shared__ float Bs[2][32][68];
    int b = blockIdx.z;
    int n0 = blockIdx.x * 64, m0 = blockIdx.y * 64;
    int sid = ((unsigned)g_uid[b]) % NSHARD;
    const float* Wg = Wq + (size_t)sid * IND * QO;
    int tid = threadIdx.x;
    int lane = tid & 31, warp = tid >> 5;
    int g = lane >> 2, c = lane & 3;
    int wm = warp & 3, wn = warp >> 2;
    const float* xb = x + ((size_t)b * SS + m0) * INSZ;
    const float* pe = g_pe + b * P;
    uint32_t asb = smem_u32(&As[0][0][0]);
    uint32_t bsb = smem_u32(&Bs[0][0][0]);

    float d[4][4];
#pragma unroll
    for (int i = 0; i < 4; i++)
#pragma unroll
        for (int j = 0; j < 4; j++) d[i][j] = 0.f;

#define LOADTILE(t, buf)                                                                  \
    do {                                                                                  \
        int k0_ = (t) * 32;                                                               \
        for (int i = tid; i < 512; i += 256) {                                            \
            int row = i >> 3, k4 = (i & 7) * 4;                                           \
            const float* src = (k0_ < INSZ) ? &xb[row * INSZ + k0_ + k4]                  \
                                            : &pe[k0_ - INSZ + k4];                       \
            cpa16(asb + ((buf) * 64 * 36 + row * 36 + k4) * 4, src);                      \
        }                                                                                 \
        for (int i = tid; i < 512; i += 256) {                                            \
            int kk = i >> 4, n4 = (i & 15) * 4;                                           \
            cpa16(bsb + ((buf) * 32 * 68 + kk * 68 + n4) * 4,                             \
                  &Wg[(size_t)(k0_ + kk) * QO + n0 + n4]);                                \
        }                                                                                 \
    } while (0)

    LOADTILE(0, 0);
    cpcommit();

    for (int t = 0; t < 12; t++) {
        int buf = t & 1;
        if (t < 11) {
            LOADTILE(t + 1, buf ^ 1);
            cpcommit();
            cpwait1();
        } else {
            cpwait0();
        }
        __syncthreads();
#pragma unroll
        for (int ks = 0; ks < 4; ks++) {
            uint32_t ah[4], al[4];
            msp(As[buf][wm * 16 + g][ks * 8 + c], ah[0], al[0]);
            msp(As[buf][wm * 16 + g + 8][ks * 8 + c], ah[1], al[1]);
            msp(As[buf][wm * 16 + g][ks * 8 + c + 4], ah[2], al[2]);
            msp(As[buf][wm * 16 + g + 8][ks * 8 + c + 4], ah[3], al[3]);
#pragma unroll
            for (int nt = 0; nt < 4; nt++) {
                int nn = wn * 32 + nt * 8;
                uint32_t bh0, bl0, bh1, bl1;
                msp(Bs[buf][ks * 8 + c][nn + g], bh0, bl0);
                msp(Bs[buf][ks * 8 + c + 4][nn + g], bh1, bl1);
                mma8(d[nt], ah, bh0, bh1);
                mma8(d[nt], ah, bl0, bl1);
                mma8(d[nt], al, bh0, bh1);
            }
        }
        __syncthreads();
    }
    float* qb = g_q + ((size_t)b * SS + m0) * QO + n0;
#pragma unroll
    for (int nt = 0; nt < 4; nt++) {
        int nn = wn * 32 + nt * 8 + 2 * c;
        float2 v01 = {d[nt][0], d[nt][1]};
        float2 v23 = {d[nt][2], d[nt][3]};
        *(float2*)&qb[(size_t)(wm * 16 + g) * QO + nn] = v01;
        *(float2*)&qb[(size_t)(wm * 16 + g + 8) * QO + nn] = v23;
    }
}

// ---------------- flash-style fused attention (unchanged from R9) ----------------
__global__ __launch_bounds__(256, 2) void k_attn(const float* __restrict__ mem,
                                                 float* __restrict__ out) {
    extern __shared__ float sm[];
    float* qs = sm;
    float* ms = qs + 128 * MSP;
    float* es = ms + 128 * MSP;

    int tid = threadIdx.x;
    int lane = tid & 31, warp = tid >> 5;
    int g = lane >> 2, c = lane & 3;
    int b = blockIdx.y;
    int s0 = blockIdx.x * 32;
    int sid = ((unsigned)g_uid[b]) % NSHARD;
    const float* M = mem + (size_t)sid * MSZ * WD;
    float* ew = es + warp * (16 * ESP);
    int wrow = warp * 16;

    const float* qsrc = g_q + ((size_t)b * SS + s0) * QO;
    for (int i = tid; i < 128 * 16; i += 256) {
        int row = i >> 4, w4 = (i & 15) * 4;
        float4 v = *(const float4*)&qsrc[(size_t)(row >> 2) * QO + (row & 3) * WD + w4];
        *(float4*)&qs[row * MSP + w4] = v;
    }

    uint32_t ah[8][4], al[8][4];
    float acc[8][4];
#pragma unroll
    for (int nt = 0; nt < 8; nt++)
#pragma unroll
        for (int j = 0; j < 4; j++) acc[nt][j] = 0.f;
    float mx0 = -1e30f, mx1 = -1e30f, sm0 = 0.f, sm1 = 0.f;

    for (int ch = 0; ch < 4; ch++) {
        for (int i = tid; i < 128 * 16; i += 256) {
            int m = i >> 4, w4 = (i & 15) * 4;
            *(float4*)&ms[m * MSP + w4] = *(const float4*)&M[(size_t)(ch * 128 + m) * WD + w4];
        }
        __syncthreads();
        if (ch == 0) {
#pragma unroll
            for (int k = 0; k < 8; k++) {
                msp(qs[(wrow + g) * MSP + k * 8 + c], ah[k][0], al[k][0]);
                msp(qs[(wrow + g + 8) * MSP + k * 8 + c], ah[k][1], al[k][1]);
                msp(qs[(wrow + g) * MSP + k * 8 + c + 4], ah[k][2], al[k][2]);
                msp(qs[(wrow + g + 8) * MSP + k * 8 + c + 4], ah[k][3], al[k][3]);
            }
        }
        for (int sb = 0; sb < 8; sb++) {
            float e[2][4];
#pragma unroll
            for (int nt2 = 0; nt2 < 2; nt2++) {
                int mc = sb * 16 + nt2 * 8;
                float d[4] = {0.f, 0.f, 0.f, 0.f};
#pragma unroll
                for (int k = 0; k < 8; k++) {
                    uint32_t bh0, bl0, bh1, bl1;
                    msp(ms[(mc + g) * MSP + k * 8 + c], bh0, bl0);
                    msp(ms[(mc + g) * MSP + k * 8 + c + 4], bh1, bl1);
                    mma8(d, ah[k], bh0, bh1);
                    mma8(d, ah[k], bl0, bl1);
                    mma8(d, al[k], bh0, bh1);
                }
                e[nt2][0] = d[0]; e[nt2][1] = d[1]; e[nt2][2] = d[2]; e[nt2][3] = d[3];
            }
            float m0 = fmaxf(fmaxf(e[0][0], e[0][1]), fmaxf(e[1][0], e[1][1]));
            float m1 = fmaxf(fmaxf(e[0][2], e[0][3]), fmaxf(e[1][2], e[1][3]));
            m0 = fmaxf(m0, __shfl_xor_sync(0xffffffffu, m0, 1));
            m0 = fmaxf(m0, __shfl_xor_sync(0xffffffffu, m0, 2));
            m1 = fmaxf(m1, __shfl_xor_sync(0xffffffffu, m1, 1));
            m1 = fmaxf(m1, __shfl_xor_sync(0xffffffffu, m1, 2));
            float nm0 = fmaxf(mx0, m0), nm1 = fmaxf(mx1, m1);
            float sc0 = __expf(mx0 - nm0), sc1 = __expf(mx1 - nm1);
            sm0 *= sc0; sm1 *= sc1;
#pragma unroll
            for (int nt = 0; nt < 8; nt++) {
                acc[nt][0] *= sc0; acc[nt][1] *= sc0;
                acc[nt][2] *= sc1; acc[nt][3] *= sc1;
            }
            mx0 = nm0; mx1 = nm1;
#pragma unroll
            for (int nt2 = 0; nt2 < 2; nt2++) {
                float e0 = __expf(e[nt2][0] - nm0);
                float e1 = __expf(e[nt2][1] - nm0);
                float e2 = __expf(e[nt2][2] - nm1);
                float e3 = __expf(e[nt2][3] - nm1);
                sm0 += e0 + e1; sm1 += e2 + e3;
                int col = nt2 * 8 + 2 * c;
                float2 v01 = {e0, e1};
                float2 v23 = {e2, e3};
                *(float2*)&ew[g * ESP + col] = v01;
                *(float2*)&ew[(g + 8) * ESP + col] = v23;
            }
            __syncwarp();
#pragma unroll
            for (int kg = 0; kg < 2; kg++) {
                uint32_t a[4];
                a[0] = __float_as_uint(ew[g * ESP + kg * 8 + c]);
                a[1] = __float_as_uint(ew[(g + 8) * ESP + kg * 8 + c]);
                a[2] = __float_as_uint(ew[g * ESP + kg * 8 + c + 4]);
                a[3] = __float_as_uint(ew[(g + 8) * ESP + kg * 8 + c + 4]);
                int mr = sb * 16 + kg * 8;
#pragma unroll
                for (int nt = 0; nt < 8; nt++) {
                    int w0 = nt * 8;
                    uint32_t bh0, bl0, bh1, bl1;
                    msp(ms[(mr + c) * MSP + w0 + g], bh0, bl0);
                    msp(ms[(mr + c + 4) * MSP + w0 + g], bh1, bl1);
                    mma8(acc[nt], a, bh0, bh1);
                    mma8(acc[nt], a, bl0, bl1);
                }
            }
            __syncwarp();
        }
        __syncthreads();
    }

    sm0 += __shfl_xor_sync(0xffffffffu, sm0, 1);
    sm0 += __shfl_xor_sync(0xffffffffu, sm0, 2);
    sm1 += __shfl_xor_sync(0xffffffffu, sm1, 1);
    sm1 += __shfl_xor_sync(0xffffffffu, sm1, 2);
    float inv0 = 1.f / sm0, inv1 = 1.f / sm1;
    float* ob = out + ((size_t)b * 512 + s0 * 4) * WD;
#pragma unroll
    for (int nt = 0; nt < 8; nt++) {
        int col = nt * 8 + 2 * c;
        float2 v01 = {acc[nt][0] * inv0, acc[nt][1] * inv0};
        float2 v23 = {acc[nt][2] * inv1, acc[nt][3] * inv1};
        *(float2*)&ob[(size_t)(wrow + g) * WD + col] = v01;
        *(float2*)&ob[(size_t)(wrow + g + 8) * WD + col] = v23;
    }
}

// --- final_state for b = B-1: one block per (s,r) row, 512 blocks ---
__global__ void k_fs(const float* __restrict__ mem, float* __restrict__ out) {
    __shared__ float qr[64];
    __shared__ float red[8];
    int s = blockIdx.x >> 2, r = blockIdx.x & 3;
    int tid = threadIdx.x;
    int lane = tid & 31, warp = tid >> 5;
    int sid = ((unsigned)g_uid[BB - 1]) % NSHARD;
    const float* M = mem + (size_t)sid * MSZ * WD;
    const float* q = g_q + ((size_t)(BB - 1) * SS + s) * QO + r * WD;
    if (tid < 64) qr[tid] = q[tid];
    __syncthreads();

    float d0 = 0.f, d1 = 0.f;
    {
        const float* m0p = M + (size_t)tid * WD;
        const float* m1p = M + (size_t)(tid + 256) * WD;
#pragma unroll
        for (int w4 = 0; w4 < 64; w4 += 4) {
            float4 qv = *(const float4*)&qr[w4];
            float4 a = *(const float4*)&m0p[w4];
            float4 bq = *(const float4*)&m1p[w4];
            d0 += qv.x * a.x + qv.y * a.y + qv.z * a.z + qv.w * a.w;
            d1 += qv.x * bq.x + qv.y * bq.y + qv.z * bq.z + qv.w * bq.w;
        }
    }
    // block max
    float mx = fmaxf(d0, d1);
#pragma unroll
    for (int o = 16; o > 0; o >>= 1) mx = fmaxf(mx, __shfl_xor_sync(0xffffffffu, mx, o));
    if (lane == 0) red[warp] = mx;
    __syncthreads();
    mx = red[lane & 7];
#pragma unroll
    for (int o = 4; o > 0; o >>= 1) mx = fmaxf(mx, __shfl_xor_sync(0xffffffffu, mx, o));
    float e0 = __expf(d0 - mx), e1 = __expf(d1 - mx);
    float sum = e0 + e1;
#pragma unroll
    for (int o = 16; o > 0; o >>= 1) sum += __shfl_xor_sync(0xffffffffu, sum, o);
    __syncthreads();
    if (lane == 0) red[warp] = sum;
    __syncthreads();
    sum = red[lane & 7];
#pragma unroll
    for (int o = 4; o > 0; o >>= 1) sum += __shfl_xor_sync(0xffffffffu, sum, o);
    float inv = 1.f / sum;
    float* fs = out + (size_t)BB * SS * RR * WD + (size_t)(s * 4 + r) * MSZ;
    fs[tid] = e0 * inv;
    fs[tid + 256] = e1 * inv;
}

extern "C" void kernel_launch(void* const* d_in, const int* in_sizes, int n_in,
                              void* d_out, int out_size) {
    const float* x = (const float*)d_in[0];
    const int* uid = (const int*)d_in[1];
    const float* tab = (const float*)d_in[2];
    const float* Wp = (const float*)d_in[3];
    const float* bp = (const float*)d_in[4];
    const float* Wq = (const float*)d_in[5];
    const float* memp = (const float*)d_in[6];
    float* out = (float*)d_out;

    k_uid<<<1, 256>>>(uid);
    k_pe<<<BB, 128>>>(tab, Wp, bp);
    dim3 g2(4, 2, BB);
    k_qgemm<<<g2, 256>>>(x, Wq);
    k_fs<<<SS * RR, 256>>>(memp, out);

    const int smem_bytes = (2 * 128 * MSP + 8 * 16 * ESP) * 4;
    cudaFuncSetAttribute(k_attn, cudaFuncAttributeMaxDynamicSharedMemorySize, smem_bytes);
    dim3 g3(4, BB);
    k_attn<<<g3, 256, smem_bytes>>>(memp, out);
}

// round 11
// speedup vs baseline: 1.9434x; 1.0160x over previous
#include <cuda_runtime.h>
#include <cstdint>

#define NUSERS 100000
#define E 64
#define P 128
#define NSHARD 16
#define MSZ 512
#define WD 64
#define RR 4
#define INSZ 256
#define BB 256
#define SS 128
#define IND 384
#define QO 256

#define MSP 68
#define ESP 20

__device__ float g_pe[BB * P];
__device__ float g_q[(size_t)BB * SS * QO];
__device__ int g_uid[BB];

__global__ void k_uid(const int* __restrict__ u) {
    int s = 2;
#pragma unroll
    for (int i = 0; i < 8; i++)
        if (u[2 * i + 1] != 0) s = 1;
    int b = blockIdx.x * blockDim.x + threadIdx.x;
    if (b < BB) g_uid[b] = u[b * s];
}

__device__ __forceinline__ void msp(float x, uint32_t& h, uint32_t& l) {
    h = __float_as_uint(x) & 0xFFFFE000u;
    l = __float_as_uint(x - __uint_as_float(h));
}
__device__ __forceinline__ void mma8(float d[4], const uint32_t a[4], uint32_t b0, uint32_t b1) {
    asm volatile(
        "mma.sync.aligned.m16n8k8.row.col.f32.tf32.tf32.f32 "
        "{%0,%1,%2,%3}, {%4,%5,%6,%7}, {%8,%9}, {%0,%1,%2,%3};"
        : "+f"(d[0]), "+f"(d[1]), "+f"(d[2]), "+f"(d[3])
        : "r"(a[0]), "r"(a[1]), "r"(a[2]), "r"(a[3]), "r"(b0), "r"(b1));
}
__device__ __forceinline__ uint32_t smem_u32(const void* p) {
    uint32_t a;
    asm("{ .reg .u64 t; cvta.to.shared.u64 t, %1; cvt.u32.u64 %0, t; }" : "=r"(a) : "l"(p));
    return a;
}
__device__ __forceinline__ void cpa16(uint32_t s, const void* g) {
    asm volatile("cp.async.ca.shared.global [%0], [%1], 16;" :: "r"(s), "l"(g));
}
__device__ __forceinline__ void cpcommit() { asm volatile("cp.async.commit_group;"); }
__device__ __forceinline__ void cpwait1() { asm volatile("cp.async.wait_group 1;"); }
__device__ __forceinline__ void cpwait0() { asm volatile("cp.async.wait_group 0;"); }

__global__ void k_pe(const float* __restrict__ tab, const float* __restrict__ Wp,
                     const float* __restrict__ bp) {
    __shared__ float ue[E];
    int b = blockIdx.x;
    int t = threadIdx.x;
    int uid = g_uid[b];
    if (t < E) ue[t] = tab[(size_t)uid * E + t];
    __syncthreads();
    float acc = bp[t];
#pragma unroll
    for (int e = 0; e < E; e++) acc += ue[e] * Wp[e * P + t];
    g_pe[b * P + t] = acc;
}

// --- q = concat(x, pe) @ Wq[sid]; cp.async double-buffered, 8 acc chains ---
__global__ __launch_bounds__(256) void k_qgemm(const float* __restrict__ x,
                                               const float* __restrict__ Wq) {
    __shared__ float As[2][64][36];
    __shared__ float Bs[2][32][68];
    int b = blockIdx.z;
    int n0 = blockIdx.x * 64, m0 = blockIdx.y * 64;
    int sid = ((unsigned)g_uid[b]) % NSHARD;
    const float* Wg = Wq + (size_t)sid * IND * QO;
    int tid = threadIdx.x;
    int lane = tid & 31, warp = tid >> 5;
    int g = lane >> 2, c = lane & 3;
    int wm = warp & 3, wn = warp >> 2;
    const float* xb = x + ((size_t)b * SS + m0) * INSZ;
    const float* pe = g_pe + b * P;
    uint32_t asb = smem_u32(&As[0][0][0]);
    uint32_t bsb = smem_u32(&Bs[0][0][0]);

    float d[2][4][4];
#pragma unroll
    for (int p = 0; p < 2; p++)
#pragma unroll
        for (int i = 0; i < 4; i++)
#pragma unroll
            for (int j = 0; j < 4; j++) d[p][i][j] = 0.f;

#define LOADTILE(t, buf)                                                                  \
    do {                                                                                  \
        int k0_ = (t) * 32;                                                               \
        for (int i = tid; i < 512; i += 256) {                                            \
            int row = i >> 3, k4 = (i & 7) * 4;                                           \
            const float* src = (k0_ < INSZ) ? &xb[row * INSZ + k0_ + k4]                  \
                                            : &pe[k0_ - INSZ + k4];                       \
            cpa16(asb + ((buf) * 64 * 36 + row * 36 + k4) * 4, src);                      \
        }                                                                                 \
        for (int i = tid; i < 512; i += 256) {                                            \
            int kk = i >> 4, n4 = (i & 15) * 4;                                           \
            cpa16(bsb + ((buf) * 32 * 68 + kk * 68 + n4) * 4,                             \
                  &Wg[(size_t)(k0_ + kk) * QO + n0 + n4]);                                \
        }                                                                                 \
    } while (0)

    LOADTILE(0, 0);
    cpcommit();

    for (int t = 0; t < 12; t++) {
        int buf = t & 1;
        if (t < 11) {
            LOADTILE(t + 1, buf ^ 1);
            cpcommit();
            cpwait1();
        } else {
            cpwait0();
        }
        __syncthreads();
#pragma unroll
        for (int ks = 0; ks < 4; ks++) {
            int par = ks & 1;
            uint32_t ah[4], al[4];
            msp(As[buf][wm * 16 + g][ks * 8 + c], ah[0], al[0]);
            msp(As[buf][wm * 16 + g + 8][ks * 8 + c], ah[1], al[1]);
            msp(As[buf][wm * 16 + g][ks * 8 + c + 4], ah[2], al[2]);
            msp(As[buf][wm * 16 + g + 8][ks * 8 + c + 4], ah[3], al[3]);
#pragma unroll
            for (int nt = 0; nt < 4; nt++) {
                int nn = wn * 32 + nt * 8;
                uint32_t bh0, bl0, bh1, bl1;
                msp(Bs[buf][ks * 8 + c][nn + g], bh0, bl0);
                msp(Bs[buf][ks * 8 + c + 4][nn + g], bh1, bl1);
                mma8(d[par][nt], ah, bh0, bh1);
                mma8(d[par][nt], ah, bl0, bl1);
                mma8(d[par][nt], al, bh0, bh1);
            }
        }
        __syncthreads();
    }
    float* qb = g_q + ((size_t)b * SS + m0) * QO + n0;
#pragma unroll
    for (int nt = 0; nt < 4; nt++) {
        int nn = wn * 32 + nt * 8 + 2 * c;
        float2 v01 = {d[0][nt][0] + d[1][nt][0], d[0][nt][1] + d[1][nt][1]};
        float2 v23 = {d[0][nt][2] + d[1][nt][2], d[0][nt][3] + d[1][nt][3]};
        *(float2*)&qb[(size_t)(wm * 16 + g) * QO + nn] = v01;
        *(float2*)&qb[(size_t)(wm * 16 + g + 8) * QO + nn] = v23;
    }
}

// ---------------- flash-style fused attention + fused final_state ----------------
__global__ __launch_bounds__(256, 2) void k_attn(const float* __restrict__ mem,
                                                 float* __restrict__ out) {
    extern __shared__ float sm[];
    float* qs = sm;
    float* ms = qs + 128 * MSP;
    float* es = ms + 128 * MSP;

    int tid = threadIdx.x;
    int lane = tid & 31, warp = tid >> 5;
    int g = lane >> 2, c = lane & 3;
    int b = blockIdx.y;
    int s0 = blockIdx.x * 32;
    int sid = ((unsigned)g_uid[b]) % NSHARD;
    const float* M = mem + (size_t)sid * MSZ * WD;
    float* ew = es + warp * (16 * ESP);
    int wrow = warp * 16;

    const float* qsrc = g_q + ((size_t)b * SS + s0) * QO;
    for (int i = tid; i < 128 * 16; i += 256) {
        int row = i >> 4, w4 = (i & 15) * 4;
        float4 v = *(const float4*)&qsrc[(size_t)(row >> 2) * QO + (row & 3) * WD + w4];
        *(float4*)&qs[row * MSP + w4] = v;
    }

    uint32_t ah[8][4], al[8][4];
    float acc[8][4];
#pragma unroll
    for (int nt = 0; nt < 8; nt++)
#pragma unroll
        for (int j = 0; j < 4; j++) acc[nt][j] = 0.f;
    float mx0 = -1e30f, mx1 = -1e30f, sm0 = 0.f, sm1 = 0.f;

    for (int ch = 0; ch < 4; ch++) {
        for (int i = tid; i < 128 * 16; i += 256) {
            int m = i >> 4, w4 = (i & 15) * 4;
            *(float4*)&ms[m * MSP + w4] = *(const float4*)&M[(size_t)(ch * 128 + m) * WD + w4];
        }
        __syncthreads();
        if (ch == 0) {
#pragma unroll
            for (int k = 0; k < 8; k++) {
                msp(qs[(wrow + g) * MSP + k * 8 + c], ah[k][0], al[k][0]);
                msp(qs[(wrow + g + 8) * MSP + k * 8 + c], ah[k][1], al[k][1]);
                msp(qs[(wrow + g) * MSP + k * 8 + c + 4], ah[k][2], al[k][2]);
                msp(qs[(wrow + g + 8) * MSP + k * 8 + c + 4], ah[k][3], al[k][3]);
            }
        }
        for (int sb = 0; sb < 8; sb++) {
            float e[2][4];
#pragma unroll
            for (int nt2 = 0; nt2 < 2; nt2++) {
                int mc = sb * 16 + nt2 * 8;
                float d0[4] = {0.f, 0.f, 0.f, 0.f};
                float d1[4] = {0.f, 0.f, 0.f, 0.f};
#pragma unroll
                for (int k = 0; k < 8; k += 2) {
                    uint32_t bh0, bl0, bh1, bl1;
                    msp(ms[(mc + g) * MSP + k * 8 + c], bh0, bl0);
                    msp(ms[(mc + g) * MSP + k * 8 + c + 4], bh1, bl1);
                    mma8(d0, ah[k], bh0, bh1);
                    mma8(d0, ah[k], bl0, bl1);
                    mma8(d0, al[k], bh0, bh1);
                    uint32_t ch0, cl0, ch1, cl1;
                    msp(ms[(mc + g) * MSP + (k + 1) * 8 + c], ch0, cl0);
                    msp(ms[(mc + g) * MSP + (k + 1) * 8 + c + 4], ch1, cl1);
                    mma8(d1, ah[k + 1], ch0, ch1);
                    mma8(d1, ah[k + 1], cl0, cl1);
                    mma8(d1, al[k + 1], ch0, ch1);
                }
#pragma unroll
                for (int j = 0; j < 4; j++) e[nt2][j] = d0[j] + d1[j];
            }
            float m0 = fmaxf(fmaxf(e[0][0], e[0][1]), fmaxf(e[1][0], e[1][1]));
            float m1 = fmaxf(fmaxf(e[0][2], e[0][3]), fmaxf(e[1][2], e[1][3]));
            m0 = fmaxf(m0, __shfl_xor_sync(0xffffffffu, m0, 1));
            m0 = fmaxf(m0, __shfl_xor_sync(0xffffffffu, m0, 2));
            m1 = fmaxf(m1, __shfl_xor_sync(0xffffffffu, m1, 1));
            m1 = fmaxf(m1, __shfl_xor_sync(0xffffffffu, m1, 2));
            float nm0 = fmaxf(mx0, m0), nm1 = fmaxf(mx1, m1);
            float sc0 = __expf(mx0 - nm0), sc1 = __expf(mx1 - nm1);
            sm0 *= sc0; sm1 *= sc1;
#pragma unroll
            for (int nt = 0; nt < 8; nt++) {
                acc[nt][0] *= sc0; acc[nt][1] *= sc0;
                acc[nt][2] *= sc1; acc[nt][3] *= sc1;
            }
            mx0 = nm0; mx1 = nm1;
#pragma unroll
            for (int nt2 = 0; nt2 < 2; nt2++) {
                float e0 = __expf(e[nt2][0] - nm0);
                float e1 = __expf(e[nt2][1] - nm0);
                float e2 = __expf(e[nt2][2] - nm1);
                float e3 = __expf(e[nt2][3] - nm1);
                sm0 += e0 + e1; sm1 += e2 + e3;
                int col = nt2 * 8 + 2 * c;
                float2 v01 = {e0, e1};
                float2 v23 = {e2, e3};
                *(float2*)&ew[g * ESP + col] = v01;
                *(float2*)&ew[(g + 8) * ESP + col] = v23;
            }
            __syncwarp();
#pragma unroll
            for (int kg = 0; kg < 2; kg++) {
                uint32_t a[4];
                a[0] = __float_as_uint(ew[g * ESP + kg * 8 + c]);
                a[1] = __float_as_uint(ew[(g + 8) * ESP + kg * 8 + c]);
                a[2] = __float_as_uint(ew[g * ESP + kg * 8 + c + 4]);
                a[3] = __float_as_uint(ew[(g + 8) * ESP + kg * 8 + c + 4]);
                int mr = sb * 16 + kg * 8;
#pragma unroll
                for (int nt = 0; nt < 8; nt++) {
                    int w0 = nt * 8;
                    uint32_t bh0, bl0, bh1, bl1;
                    msp(ms[(mr + c) * MSP + w0 + g], bh0, bl0);
                    msp(ms[(mr + c + 4) * MSP + w0 + g], bh1, bl1);
                    mma8(acc[nt], a, bh0, bh1);
                    mma8(acc[nt], a, bl0, bl1);
                }
            }
            __syncwarp();
        }
        __syncthreads();
    }

    sm0 += __shfl_xor_sync(0xffffffffu, sm0, 1);
    sm0 += __shfl_xor_sync(0xffffffffu, sm0, 2);
    sm1 += __shfl_xor_sync(0xffffffffu, sm1, 1);
    sm1 += __shfl_xor_sync(0xffffffffu, sm1, 2);
    float inv0 = 1.f / sm0, inv1 = 1.f / sm1;
    float* ob = out + ((size_t)b * 512 + s0 * 4) * WD;
#pragma unroll
    for (int nt = 0; nt < 8; nt++) {
        int col = nt * 8 + 2 * c;
        float2 v01 = {acc[nt][0] * inv0, acc[nt][1] * inv0};
        float2 v23 = {acc[nt][2] * inv1, acc[nt][3] * inv1};
        *(float2*)&ob[(size_t)(wrow + g) * WD + col] = v01;
        *(float2*)&ob[(size_t)(wrow + g + 8) * WD + col] = v23;
    }

    // ---- fused final_state (b == B-1 only, 4 blocks): recompute scores, mx/sum final ----
    if (b == BB - 1) {
        float* fs = out + (size_t)BB * SS * RR * WD;
        for (int ch = 0; ch < 4; ch++) {
            for (int i = tid; i < 128 * 16; i += 256) {
                int m = i >> 4, w4 = (i & 15) * 4;
                *(float4*)&ms[m * MSP + w4] = *(const float4*)&M[(size_t)(ch * 128 + m) * WD + w4];
            }
            __syncthreads();
            for (int sb = 0; sb < 8; sb++) {
#pragma unroll
                for (int nt2 = 0; nt2 < 2; nt2++) {
                    int mc = sb * 16 + nt2 * 8;
                    float d[4] = {0.f, 0.f, 0.f, 0.f};
#pragma unroll
                    for (int k = 0; k < 8; k++) {
                        uint32_t bh0, bl0, bh1, bl1;
                        msp(ms[(mc + g) * MSP + k * 8 + c], bh0, bl0);
                        msp(ms[(mc + g) * MSP + k * 8 + c + 4], bh1, bl1);
                        mma8(d, ah[k], bh0, bh1);
                        mma8(d, ah[k], bl0, bl1);
                        mma8(d, al[k], bh0, bh1);
                    }
                    int col = ch * 128 + mc + 2 * c;
                    float2 v01 = {__expf(d[0] - mx0) * inv0, __expf(d[1] - mx0) * inv0};
                    float2 v23 = {__expf(d[2] - mx1) * inv1, __expf(d[3] - mx1) * inv1};
                    *(float2*)&fs[(size_t)(s0 * 4 + wrow + g) * MSZ + col] = v01;
                    *(float2*)&fs[(size_t)(s0 * 4 + wrow + g + 8) * MSZ + col] = v23;
                }
            }
            __syncthreads();
        }
    }
}

extern "C" void kernel_launch(void* const* d_in, const int* in_sizes, int n_in,
                              void* d_out, int out_size) {
    const float* x = (const float*)d_in[0];
    const int* uid = (const int*)d_in[1];
    const float* tab = (const float*)d_in[2];
    const float* Wp = (const float*)d_in[3];
    const float* bp = (const float*)d_in[4];
    const float* Wq = (const float*)d_in[5];
    const float* memp = (const float*)d_in[6];
    float* out = (float*)d_out;

    k_uid<<<1, 256>>>(uid);
    k_pe<<<BB, 128>>>(tab, Wp, bp);
    dim3 g2(4, 2, BB);
    k_qgemm<<<g2, 256>>>(x, Wq);

    const int smem_bytes = (2 * 128 * MSP + 8 * 16 * ESP) * 4;
    cudaFuncSetAttribute(k_attn, cudaFuncAttributeMaxDynamicSharedMemorySize, smem_bytes);
    dim3 g3(4, BB);
    k_attn<<<g3, 256, smem_bytes>>>(memp, out);
}